// round 15
// baseline (speedup 1.0000x reference)
#include <cuda_runtime.h>
#include <cuda_bf16.h>
#include <cstdint>

// Fixed problem shape: x [B=64, C=1, H=64, W=2048] f32
#define H_DIM 64
#define W_DIM 2048
#define R_STRIP 4
#define COLS 4                  // columns per thread
#define TPB 256                 // threads per block
#define WSPAN (TPB * COLS)      // 1024 cols per tile
#define XBLKS (W_DIM / WSPAN)   // 2
#define STRIPS (H_DIM / R_STRIP) // 16
#define NBLK 592                // persistent blocks; launch_bounds(256,6) guarantees 888 resident >= 592
#define LOG2E 1.4426950408889634f

// 2*exp(-0.5*sqrt(2)) and 2*exp(-0.5)  (the 2x from the sigmoid folded into weights)
#define WX2 0.9861373827905206f
#define WC2 1.2130613194252668f

// Persistent state. Zero-initialized at module load; the barrier protocol restores
// done/tick to 0 every launch (sense-reversal on g_flag), so graph replays are safe.
__device__ __align__(16) float g_blockmin[NBLK];
__device__ int g_flag;   // sense flag, flips once per launch
__device__ int g_done;   // arrival counter, reset by releaser each launch
__device__ int g_tick;   // phase-2 work ticket, reset by releaser each launch
__device__ float g_ngl;  // -gmin * log2e

__device__ __forceinline__ float ex2f(float x) {
    float r;
    asm("ex2.approx.f32 %0, %1;" : "=f"(r) : "f"(x));
    return r;
}

__device__ __forceinline__ void load_row(const float* __restrict__ row, int c0, float v[COLS + 2]) {
    float4 a = __ldg(reinterpret_cast<const float4*>(row + c0));
    v[1] = a.x; v[2] = a.y; v[3] = a.z; v[4] = a.w;
    v[0] = (c0 > 0) ? __ldg(row + c0 - 1) : 0.0f;
    v[5] = (c0 + COLS < W_DIM) ? __ldg(row + c0 + COLS) : 0.0f;
}

__device__ __forceinline__ void store_row(float* __restrict__ o, const float v[COLS + 2]) {
    *reinterpret_cast<float4*>(o) = make_float4(v[1], v[2], v[3], v[4]);
}

// per-row horizontal stencils: T over v*q, U over q  (weights fold the 2x)
__device__ __forceinline__ void stencil_row(const float v[COLS + 2], float ngl,
                                            float T[COLS], float U[COLS]) {
    float q[COLS + 2], p[COLS + 2];
    #pragma unroll
    for (int i = 0; i < COLS + 2; i++) {
        // exp(v - gmin) = 2^(v*log2e - gmin*log2e);  ngl = -gmin*log2e
        float e = ex2f(fmaf(v[i], LOG2E, ngl));
        float qi = (v[i] != 0.0f) ? __fdividef(1.0f, 1.0f + e) : 0.0f;
        q[i] = qi;
        p[i] = v[i] * qi;
    }
    #pragma unroll
    for (int j = 0; j < COLS; j++) {
        T[j] = WX2 * (p[j] + p[j + 2]) + WC2 * p[j + 1];
        U[j] = WX2 * (q[j] + q[j + 2]) + WC2 * q[j + 1];
    }
}

__device__ __forceinline__ void process_tile(int t, float ngl,
                                             const float* __restrict__ x,
                                             float* __restrict__ out, int tid) {
    const int xblk  = t & (XBLKS - 1);
    const int strip = (t >> 1) & (STRIPS - 1);
    const int b     = t >> 5;           // XBLKS*STRIPS = 32 tiles per batch

    const int c0 = xblk * WSPAN + tid * COLS;
    const int hp0 = strip * R_STRIP;

    const float* __restrict__ base = x + (long)b * H_DIM * W_DIM;
    float* __restrict__ obase = out + (long)b * 2 * H_DIM * W_DIM;

    float v[COLS + 2], Tp[COLS], Up[COLS];

    load_row(base + (long)hp0 * W_DIM, c0, v);
    stencil_row(v, ngl, Tp, Up);
    store_row(obase + (long)(2 * hp0) * W_DIM + c0, v);

    #pragma unroll
    for (int r = 1; r <= R_STRIP; r++) {
        const int h = hp0 + r;
        if (h < H_DIM) {
            load_row(base + (long)h * W_DIM, c0, v);
            if (r < R_STRIP)
                store_row(obase + (long)(2 * h) * W_DIM + c0, v);

            float Tc[COLS], Uc[COLS];
            stencil_row(v, ngl, Tc, Uc);

            float rr[COLS];
            #pragma unroll
            for (int j = 0; j < COLS; j++) {
                float den = Up[j] + Uc[j];
                rr[j] = __fdividef(Tp[j] + Tc[j], (den == 0.0f) ? 1.0f : den);
            }
            float* outO = obase + (long)(2 * h - 1) * W_DIM + c0;
            *reinterpret_cast<float4*>(outO) = make_float4(rr[0], rr[1], rr[2], rr[3]);

            #pragma unroll
            for (int j = 0; j < COLS; j++) { Tp[j] = Tc[j]; Up[j] = Uc[j]; }
        } else {
            // last strip only: odd row 2H-1 duplicates x's last row (L1-hot reload)
            const float* rowL = base + (long)(H_DIM - 1) * W_DIM + c0;
            float4 a = __ldg(reinterpret_cast<const float4*>(rowL));
            float* outO = obase + (long)(2 * H_DIM - 1) * W_DIM + c0;
            *reinterpret_cast<float4*>(outO) = a;
        }
    }
}

__global__ void __launch_bounds__(TPB, 6) fused_kernel(const float* __restrict__ x,
                                                       float* __restrict__ out,
                                                       int n4, int ntiles) {
    const int tid = threadIdx.x;
    const int bid = blockIdx.x;
    __shared__ float sm[8];
    __shared__ int s_last;
    __shared__ float s_ngl;
    __shared__ int s_tile;

    // ---------------- Phase 1: grid-stride min over x ----------------
    {
        float m = 3.4e38f;
        const float4* __restrict__ x4 = reinterpret_cast<const float4*>(x);
        for (int i = bid * TPB + tid; i < n4; i += NBLK * TPB) {
            float4 v = __ldg(x4 + i);
            m = fminf(m, fminf(fminf(v.x, v.y), fminf(v.z, v.w)));
        }
        #pragma unroll
        for (int off = 16; off > 0; off >>= 1)
            m = fminf(m, __shfl_xor_sync(0xFFFFFFFFu, m, off));
        int lane = tid & 31, wid = tid >> 5;
        if (lane == 0) sm[wid] = m;
        __syncthreads();
        if (tid == 0) {
            m = sm[0];
            #pragma unroll
            for (int i = 1; i < 8; i++) m = fminf(m, sm[i]);
            g_blockmin[bid] = m;
        }
    }

    // ---------------- Global barrier (sense reversal, replay-safe) ----------------
    int sense = 0;
    if (tid == 0) {
        sense = *(volatile int*)&g_flag;     // read sense BEFORE arrival
        __threadfence();                     // publish g_blockmin[bid]
        int prev = atomicAdd(&g_done, 1);
        s_last = (prev == NBLK - 1);
    }
    __syncthreads();

    if (s_last) {
        // last-arriving block: final reduce over 592 block minima
        float m = 3.4e38f;
        for (int i = tid; i < NBLK; i += TPB)
            m = fminf(m, g_blockmin[i]);
        #pragma unroll
        for (int off = 16; off > 0; off >>= 1)
            m = fminf(m, __shfl_xor_sync(0xFFFFFFFFu, m, off));
        int lane = tid & 31, wid = tid >> 5;
        if (lane == 0) sm[wid] = m;
        __syncthreads();
        if (tid == 0) {
            m = sm[0];
            #pragma unroll
            for (int i = 1; i < 8; i++) m = fminf(m, sm[i]);
            // padded zeros participate in the global min
            g_ngl = -fminf(m, 0.0f) * LOG2E;
            g_done = 0;          // reset for next graph replay
            g_tick = 0;          // reset phase-2 ticket
            __threadfence();
            *(volatile int*)&g_flag = sense ^ 1;   // release
        }
        __syncthreads();
    } else {
        if (tid == 0) {
            while (*(volatile int*)&g_flag == sense)
                __nanosleep(64);
        }
        __syncthreads();
    }
    __threadfence();
    if (tid == 0) s_ngl = *(volatile float*)&g_ngl;
    __syncthreads();
    const float ngl = s_ngl;

    // ---------------- Phase 2: ticket-based strip tiles ----------------
    for (;;) {
        if (tid == 0) s_tile = atomicAdd(&g_tick, 1);
        __syncthreads();
        const int t = s_tile;
        if (t >= ntiles) break;
        process_tile(t, ngl, x, out, tid);
        __syncthreads();   // protect s_tile reuse
    }
}

extern "C" void kernel_launch(void* const* d_in, const int* in_sizes, int n_in,
                              void* d_out, int out_size) {
    const float* x = (const float*)d_in[0];
    float* out = (float*)d_out;

    const int n = in_sizes[0];
    const int B = n / (H_DIM * W_DIM);
    const int ntiles = XBLKS * STRIPS * B;   // 2048 for B=64

    fused_kernel<<<NBLK, TPB>>>(x, out, n / 4, ntiles);
}

// round 16
// speedup vs baseline: 1.0560x; 1.0560x over previous
#include <cuda_runtime.h>
#include <cuda_bf16.h>
#include <cstdint>

// Fixed problem shape: x [B=64, C=1, H=64, W=2048] f32
#define H_DIM 64
#define W_DIM 2048
#define NBLK_MIN 1024
#define R_STRIP 4
#define COLS 4          // columns per thread
#define TPB 256         // threads per block
#define WSPAN (TPB * COLS)   // 1024 cols per block
#define LOG2E 1.4426950408889634f

// 2*exp(-0.5*sqrt(2)) and 2*exp(-0.5)  (the 2x from the sigmoid folded into weights)
#define WX2 0.9861373827905206f
#define WC2 1.2130613194252668f

__device__ __align__(16) float g_blockmin[NBLK_MIN];

// ---------------- packed f32x2 helpers (Blackwell) ----------------
typedef unsigned long long u64;

__device__ __forceinline__ u64 pk2(float lo, float hi) {
    u64 r; asm("mov.b64 %0, {%1, %2};" : "=l"(r) : "f"(lo), "f"(hi)); return r;
}
__device__ __forceinline__ void upk2(u64 v, float& lo, float& hi) {
    asm("mov.b64 {%0, %1}, %2;" : "=f"(lo), "=f"(hi) : "l"(v));
}
__device__ __forceinline__ u64 add2(u64 a, u64 b) {
    u64 r; asm("add.rn.f32x2 %0, %1, %2;" : "=l"(r) : "l"(a), "l"(b)); return r;
}
__device__ __forceinline__ u64 mul2(u64 a, u64 b) {
    u64 r; asm("mul.rn.f32x2 %0, %1, %2;" : "=l"(r) : "l"(a), "l"(b)); return r;
}
__device__ __forceinline__ u64 fma2(u64 a, u64 b, u64 c) {
    u64 r; asm("fma.rn.f32x2 %0, %1, %2, %3;" : "=l"(r) : "l"(a), "l"(b), "l"(c)); return r;
}
__device__ __forceinline__ float ex2f(float x) {
    float r; asm("ex2.approx.f32 %0, %1;" : "=f"(r) : "f"(x)); return r;
}

// ---------------- Pass 1: per-block minima (plain stores, no init needed) ---------
__global__ void __launch_bounds__(256) min_reduce_kernel(const float* __restrict__ x, int n4) {
    int gid = blockIdx.x * blockDim.x + threadIdx.x;
    int stride = gridDim.x * blockDim.x;
    float m = 3.4e38f;
    const float4* __restrict__ x4 = reinterpret_cast<const float4*>(x);
    for (int i = gid; i < n4; i += stride) {
        float4 v = __ldg(x4 + i);
        m = fminf(m, fminf(fminf(v.x, v.y), fminf(v.z, v.w)));
    }
    #pragma unroll
    for (int off = 16; off > 0; off >>= 1)
        m = fminf(m, __shfl_xor_sync(0xFFFFFFFFu, m, off));
    __shared__ float sm[8];
    int lane = threadIdx.x & 31;
    int wid = threadIdx.x >> 5;
    if (lane == 0) sm[wid] = m;
    __syncthreads();
    if (wid == 0) {
        m = (lane < 8) ? sm[lane] : 3.4e38f;
        #pragma unroll
        for (int off = 4; off > 0; off >>= 1)
            m = fminf(m, __shfl_xor_sync(0xFFFFFFFFu, m, off));
        if (lane == 0) g_blockmin[blockIdx.x] = m;
    }
}

// ---------------- Pass 2: strip kernel, packed (T,U) stencils ---------------------

__device__ __forceinline__ void load_row(const float* __restrict__ row, int c0, float v[COLS + 2]) {
    float4 a = __ldg(reinterpret_cast<const float4*>(row + c0));
    v[1] = a.x; v[2] = a.y; v[3] = a.z; v[4] = a.w;
    v[0] = (c0 > 0) ? __ldg(row + c0 - 1) : 0.0f;
    v[5] = (c0 + COLS < W_DIM) ? __ldg(row + c0 + COLS) : 0.0f;
}

__device__ __forceinline__ void store_row(float* __restrict__ o, const float v[COLS + 2]) {
    *reinterpret_cast<float4*>(o) = make_float4(v[1], v[2], v[3], v[4]);
}

// per-row horizontal stencils, packed: TU[j] = (T[j], U[j]) over (v*q, q)
__device__ __forceinline__ void stencil_row(const float v[COLS + 2], float ngl,
                                            u64 wx2, u64 wc2, u64 TU[COLS]) {
    u64 pq[COLS + 2];
    #pragma unroll
    for (int i = 0; i < COLS + 2; i++) {
        // exp(v - gmin) = 2^(v*log2e - gmin*log2e);  ngl = -gmin*log2e
        float e = ex2f(fmaf(v[i], LOG2E, ngl));
        float qi = (v[i] != 0.0f) ? __fdividef(1.0f, 1.0f + e) : 0.0f;
        pq[i] = pk2(v[i] * qi, qi);
    }
    #pragma unroll
    for (int j = 0; j < COLS; j++)
        TU[j] = fma2(wc2, pq[j + 1], mul2(wx2, add2(pq[j], pq[j + 2])));
}

// grid: (W/WSPAN, H/R_STRIP, B), block 256. Thread owns 4 cols; block owns 4 pixel rows.
__global__ void __launch_bounds__(256, 6) upsample_conv_kernel(const float* __restrict__ x,
                                                               float* __restrict__ out) {
    __shared__ float s_ngl;
    __shared__ float sm[8];
    const int tid = threadIdx.x;

    // Reduce the 1024 block-minima (L2-hot, 4KB) + padded zeros -> gmin
    {
        float4 v = *reinterpret_cast<const float4*>(g_blockmin + tid * 4);
        float m = fminf(fminf(v.x, v.y), fminf(v.z, v.w));
        #pragma unroll
        for (int off = 16; off > 0; off >>= 1)
            m = fminf(m, __shfl_xor_sync(0xFFFFFFFFu, m, off));
        int lane = tid & 31, wid = tid >> 5;
        if (lane == 0) sm[wid] = m;
        __syncthreads();
        if (tid == 0) {
            m = sm[0];
            #pragma unroll
            for (int i = 1; i < 8; i++) m = fminf(m, sm[i]);
            // padded zeros participate in the global min; store -gmin*log2e
            s_ngl = -fminf(m, 0.0f) * LOG2E;
        }
        __syncthreads();
    }
    const float ngl = s_ngl;
    const u64 wx2 = pk2(WX2, WX2);
    const u64 wc2 = pk2(WC2, WC2);

    const int c0 = blockIdx.x * WSPAN + tid * COLS;
    const int hp0 = blockIdx.y * R_STRIP;
    const int b = blockIdx.z;

    const float* __restrict__ base = x + (long)b * H_DIM * W_DIM;
    float* __restrict__ obase = out + (long)b * 2 * H_DIM * W_DIM;

    float v[COLS + 2];
    u64 TUp[COLS];

    // row hp0: sigmoid once, emit its even-row copy
    load_row(base + (long)hp0 * W_DIM, c0, v);
    stencil_row(v, ngl, wx2, wc2, TUp);
    store_row(obase + (long)(2 * hp0) * W_DIM + c0, v);

    #pragma unroll
    for (int r = 1; r <= R_STRIP; r++) {
        const int h = hp0 + r;
        if (h < H_DIM) {
            load_row(base + (long)h * W_DIM, c0, v);
            if (r < R_STRIP)    // row h's even copy belongs to this strip only for r<R_STRIP
                store_row(obase + (long)(2 * h) * W_DIM + c0, v);

            u64 TUc[COLS];
            stencil_row(v, ngl, wx2, wc2, TUc);

            float rr[COLS];
            #pragma unroll
            for (int j = 0; j < COLS; j++) {
                float num, den;
                upk2(add2(TUp[j], TUc[j]), num, den);
                rr[j] = __fdividef(num, (den == 0.0f) ? 1.0f : den);
            }
            float* outO = obase + (long)(2 * h - 1) * W_DIM + c0;
            *reinterpret_cast<float4*>(outO) = make_float4(rr[0], rr[1], rr[2], rr[3]);

            #pragma unroll
            for (int j = 0; j < COLS; j++) TUp[j] = TUc[j];
        } else {
            // only the last strip (h == H): odd row 127 duplicates x's last row (L1-hot reload)
            const float* rowL = base + (long)(H_DIM - 1) * W_DIM + c0;
            float4 a = __ldg(reinterpret_cast<const float4*>(rowL));
            float* outO = obase + (long)(2 * H_DIM - 1) * W_DIM + c0;
            *reinterpret_cast<float4*>(outO) = a;
        }
    }
}

extern "C" void kernel_launch(void* const* d_in, const int* in_sizes, int n_in,
                              void* d_out, int out_size) {
    const float* x = (const float*)d_in[0];
    float* out = (float*)d_out;

    const int n = in_sizes[0];
    const int B = n / (H_DIM * W_DIM);

    min_reduce_kernel<<<NBLK_MIN, 256>>>(x, n / 4);

    dim3 grid(W_DIM / WSPAN, H_DIM / R_STRIP, B);
    upsample_conv_kernel<<<grid, TPB>>>(x, out);
}